// round 16
// baseline (speedup 1.0000x reference)
#include <cuda_runtime.h>
#include <cuda_bf16.h>
#include <cstdint>

#define NN 50000
#define NE 800000
#define FI 112
#define DM 32
#define NG 256
#define BN_EPS 1e-5f
#define SCAN_BLK 1024
#define SCAN_NBLK ((NN + SCAN_BLK - 1) / SCAN_BLK)   // 49

typedef unsigned long long u64;

// ---------------- device scratch ----------------
__device__ float  g_Y1[NN * FI];
__device__ float  g_H [NN * FI];
__device__ float  g_Y2[NN * DM];
__device__ double g_sum1[FI], g_sq1[FI];
__device__ double g_sum2[DM], g_sq2[DM];
__device__ float  g_k2c[DM];
__device__ float  g_pool[NG * DM];
__device__ int    g_cnt[NG];
__device__ int    g_deg[NN];          // zero-init at load; consume-reset by scanA
__device__ int    g_rowptr[NN + 1];
__device__ int    g_cursor[NN];
__device__ int    g_col[NE];
__device__ int    g_blocksum[SCAN_NBLK];

// ---------------- CSR build ----------------
__global__ void hist_kernel(const int* __restrict__ dst, int E) {
    int e = blockIdx.x * blockDim.x + threadIdx.x;
    if (e < E) atomicAdd(&g_deg[dst[e]], 1);
}

__global__ __launch_bounds__(SCAN_BLK) void scanA_kernel() {
    __shared__ int wsum[32];
    int t = threadIdx.x;
    int idx = blockIdx.x * SCAN_BLK + t;
    int v = 0;
    if (idx < NN) {
        v = g_deg[idx];
        g_deg[idx] = 0;
    }
    int lane = t & 31, wid = t >> 5;
    int p = v;
#pragma unroll
    for (int d = 1; d < 32; d <<= 1) {
        int n = __shfl_up_sync(0xffffffffu, p, d);
        if (lane >= d) p += n;
    }
    if (lane == 31) wsum[wid] = p;
    __syncthreads();
    if (wid == 0) {
        int w = wsum[lane];
#pragma unroll
        for (int d = 1; d < 32; d <<= 1) {
            int n = __shfl_up_sync(0xffffffffu, w, d);
            if (lane >= d) w += n;
        }
        wsum[lane] = w;
    }
    __syncthreads();
    int excl = (p - v) + (wid ? wsum[wid - 1] : 0);
    if (idx < NN) g_rowptr[idx] = excl;
    if (t == SCAN_BLK - 1) g_blocksum[blockIdx.x] = excl + v;
}

__global__ __launch_bounds__(SCAN_BLK) void scanC_kernel() {
    __shared__ int es[SCAN_NBLK + 1];
    int t = threadIdx.x;
    if (t == 0) {
        int run = 0;
#pragma unroll 1
        for (int i = 0; i < SCAN_NBLK; i++) {
            es[i] = run;
            run += g_blocksum[i];
        }
        es[SCAN_NBLK] = run;
    }
    __syncthreads();
    int idx = blockIdx.x * SCAN_BLK + t;
    if (idx < NN) {
        int r = g_rowptr[idx] + es[blockIdx.x];
        g_rowptr[idx] = r;
        g_cursor[idx] = r;
    }
    if (blockIdx.x == SCAN_NBLK - 1 && t == 0)
        g_rowptr[NN] = es[SCAN_NBLK];
}

__global__ void fill_kernel(const int* __restrict__ src, const int* __restrict__ dst, int E) {
    int e = blockIdx.x * blockDim.x + threadIdx.x;
    if (e < E) {
        int p = atomicAdd(&g_cursor[dst[e]], 1);
        g_col[p] = src[e];
    }
}

// ---------------- gemm112: Y1 = x @ W11, 128-row tiles (R11 best) ----------------
__global__ __launch_bounds__(256) void gemm112_kernel(const float* __restrict__ A,
                                                      const float* __restrict__ W,
                                                      float* __restrict__ C, int M) {
    __shared__ __align__(16) float As[16][132];
    __shared__ __align__(16) float Ws[16][112];
    const int tid = threadIdx.x;
    const int tr = tid >> 4;
    const int tc = tid & 15;
    const int row0 = blockIdx.x * 128;

    if (blockIdx.x == 0 && tid < FI) { g_sum1[tid] = 0.0; g_sq1[tid] = 0.0; }

    u64 acc01[7], acc23[7], acc45[7], acc67[7];
#pragma unroll
    for (int j = 0; j < 7; j++) { acc01[j] = 0ull; acc23[j] = 0ull; acc45[j] = 0ull; acc67[j] = 0ull; }

    for (int kc = 0; kc < 112; kc += 16) {
#pragma unroll
        for (int i = 0; i < 2; i++) {
            int idx = tid + i * 256;
            int r = idx >> 2;
            int kq = (idx & 3) << 2;
            float4 v = make_float4(0.f, 0.f, 0.f, 0.f);
            if (row0 + r < M)
                v = *reinterpret_cast<const float4*>(A + (size_t)(row0 + r) * FI + kc + kq);
            As[kq + 0][r] = v.x;
            As[kq + 1][r] = v.y;
            As[kq + 2][r] = v.z;
            As[kq + 3][r] = v.w;
        }
#pragma unroll
        for (int i = 0; i < 7; i++) {
            int idx = tid + i * 256;
            int c = idx % 112, kk = idx / 112;
            Ws[kk][c] = W[(size_t)(kc + kk) * 112 + c];
        }
        __syncthreads();
#pragma unroll
        for (int kk = 0; kk < 16; kk++) {
            float4 alo = *reinterpret_cast<const float4*>(&As[kk][tr * 8]);
            float4 ahi = *reinterpret_cast<const float4*>(&As[kk][tr * 8 + 4]);
            u64 a01, a23, a45, a67;
            asm("mov.b64 %0, {%1, %2};" : "=l"(a01) : "f"(alo.x), "f"(alo.y));
            asm("mov.b64 %0, {%1, %2};" : "=l"(a23) : "f"(alo.z), "f"(alo.w));
            asm("mov.b64 %0, {%1, %2};" : "=l"(a45) : "f"(ahi.x), "f"(ahi.y));
            asm("mov.b64 %0, {%1, %2};" : "=l"(a67) : "f"(ahi.z), "f"(ahi.w));
#pragma unroll
            for (int j = 0; j < 7; j++) {
                float wv = Ws[kk][tc * 7 + j];
                u64 wp;
                asm("mov.b64 %0, {%1, %1};" : "=l"(wp) : "f"(wv));
                asm("fma.rn.f32x2 %0, %1, %2, %0;" : "+l"(acc01[j]) : "l"(a01), "l"(wp));
                asm("fma.rn.f32x2 %0, %1, %2, %0;" : "+l"(acc23[j]) : "l"(a23), "l"(wp));
                asm("fma.rn.f32x2 %0, %1, %2, %0;" : "+l"(acc45[j]) : "l"(a45), "l"(wp));
                asm("fma.rn.f32x2 %0, %1, %2, %0;" : "+l"(acc67[j]) : "l"(a67), "l"(wp));
            }
        }
        __syncthreads();
    }

    const int r0 = row0 + tr * 8;
#pragma unroll
    for (int j = 0; j < 7; j++) {
        int c = tc * 7 + j;
        float v[8];
        asm("mov.b64 {%0, %1}, %2;" : "=f"(v[0]), "=f"(v[1]) : "l"(acc01[j]));
        asm("mov.b64 {%0, %1}, %2;" : "=f"(v[2]), "=f"(v[3]) : "l"(acc23[j]));
        asm("mov.b64 {%0, %1}, %2;" : "=f"(v[4]), "=f"(v[5]) : "l"(acc45[j]));
        asm("mov.b64 {%0, %1}, %2;" : "=f"(v[6]), "=f"(v[7]) : "l"(acc67[j]));
#pragma unroll
        for (int i = 0; i < 8; i++)
            if (r0 + i < M) C[(size_t)(r0 + i) * 112 + c] = v[i];
    }
}

// ---------------- fused aggGemm112: direct gather + GEMM with 32-k W chunks ----------------
#define ACOL(k, r) (((((r) >> 2) ^ ((k) & 15)) << 2) | ((r) & 3))
__global__ __launch_bounds__(256) void aggGemm112_kernel(const float* __restrict__ Y1,
                                                         const float* __restrict__ b1,
                                                         const float* __restrict__ W,
                                                         const float* __restrict__ bias,
                                                         float* __restrict__ C, int M) {
    __shared__ __align__(16) float As[112 * 68];     // 30464 B
    __shared__ __align__(16) float Ws[32][112];      // 14336 B
    const int tid = threadIdx.x;
    const int tr = tid >> 4;
    const int tc = tid & 15;
    const int w    = tid >> 5;
    const int lane = tid & 31;
    const int row0 = blockIdx.x * 64;

    {
        bool act = lane < 28;
        size_t foff = (size_t)(lane << 2);
        float4 bia = make_float4(0.f, 0.f, 0.f, 0.f);
        if (act) bia = *reinterpret_cast<const float4*>(b1 + foff);
#pragma unroll 1
        for (int rr = 0; rr < 8; rr++) {
            int r = w * 8 + rr;
            int gr = row0 + r;
            float4 acc  = make_float4(0.f, 0.f, 0.f, 0.f);
            float4 acc1 = acc, acc2 = acc, acc3 = acc;
            if (gr < M) {
                int beg = __ldg(&g_rowptr[gr]);
                int end = __ldg(&g_rowptr[gr + 1]);
                if (act) acc = *reinterpret_cast<const float4*>(Y1 + (size_t)gr * FI + foff);
                int e = beg;
                for (; e + 8 <= end; e += 8) {
                    int s0 = __ldg(&g_col[e + 0]);
                    int s1 = __ldg(&g_col[e + 1]);
                    int s2 = __ldg(&g_col[e + 2]);
                    int s3 = __ldg(&g_col[e + 3]);
                    int s4 = __ldg(&g_col[e + 4]);
                    int s5 = __ldg(&g_col[e + 5]);
                    int s6 = __ldg(&g_col[e + 6]);
                    int s7 = __ldg(&g_col[e + 7]);
                    if (act) {
                        float4 v0 = *reinterpret_cast<const float4*>(Y1 + (size_t)s0 * FI + foff);
                        float4 v1 = *reinterpret_cast<const float4*>(Y1 + (size_t)s1 * FI + foff);
                        float4 v2 = *reinterpret_cast<const float4*>(Y1 + (size_t)s2 * FI + foff);
                        float4 v3 = *reinterpret_cast<const float4*>(Y1 + (size_t)s3 * FI + foff);
                        float4 v4 = *reinterpret_cast<const float4*>(Y1 + (size_t)s4 * FI + foff);
                        float4 v5 = *reinterpret_cast<const float4*>(Y1 + (size_t)s5 * FI + foff);
                        float4 v6 = *reinterpret_cast<const float4*>(Y1 + (size_t)s6 * FI + foff);
                        float4 v7 = *reinterpret_cast<const float4*>(Y1 + (size_t)s7 * FI + foff);
                        acc.x += v0.x + v4.x; acc.y += v0.y + v4.y; acc.z += v0.z + v4.z; acc.w += v0.w + v4.w;
                        acc1.x += v1.x + v5.x; acc1.y += v1.y + v5.y; acc1.z += v1.z + v5.z; acc1.w += v1.w + v5.w;
                        acc2.x += v2.x + v6.x; acc2.y += v2.y + v6.y; acc2.z += v2.z + v6.z; acc2.w += v2.w + v6.w;
                        acc3.x += v3.x + v7.x; acc3.y += v3.y + v7.y; acc3.z += v3.z + v7.z; acc3.w += v3.w + v7.w;
                    }
                }
                for (; e + 4 <= end; e += 4) {
                    int s0 = __ldg(&g_col[e + 0]);
                    int s1 = __ldg(&g_col[e + 1]);
                    int s2 = __ldg(&g_col[e + 2]);
                    int s3 = __ldg(&g_col[e + 3]);
                    if (act) {
                        float4 v0 = *reinterpret_cast<const float4*>(Y1 + (size_t)s0 * FI + foff);
                        float4 v1 = *reinterpret_cast<const float4*>(Y1 + (size_t)s1 * FI + foff);
                        float4 v2 = *reinterpret_cast<const float4*>(Y1 + (size_t)s2 * FI + foff);
                        float4 v3 = *reinterpret_cast<const float4*>(Y1 + (size_t)s3 * FI + foff);
                        acc.x += v0.x; acc.y += v0.y; acc.z += v0.z; acc.w += v0.w;
                        acc1.x += v1.x; acc1.y += v1.y; acc1.z += v1.z; acc1.w += v1.w;
                        acc2.x += v2.x; acc2.y += v2.y; acc2.z += v2.z; acc2.w += v2.w;
                        acc3.x += v3.x; acc3.y += v3.y; acc3.z += v3.z; acc3.w += v3.w;
                    }
                }
                for (; e < end; e++) {
                    int s = __ldg(&g_col[e]);
                    if (act) {
                        float4 v = *reinterpret_cast<const float4*>(Y1 + (size_t)s * FI + foff);
                        acc.x += v.x; acc.y += v.y; acc.z += v.z; acc.w += v.w;
                    }
                }
            }
            if (act) {
                float t0 = fmaxf((acc.x + acc1.x) + (acc2.x + acc3.x) + bia.x, 0.f);
                float t1 = fmaxf((acc.y + acc1.y) + (acc2.y + acc3.y) + bia.y, 0.f);
                float t2 = fmaxf((acc.z + acc1.z) + (acc2.z + acc3.z) + bia.z, 0.f);
                float t3 = fmaxf((acc.w + acc1.w) + (acc2.w + acc3.w) + bia.w, 0.f);
                int k0 = lane << 2;
                As[(k0 + 0) * 68 + ACOL(k0 + 0, r)] = t0;
                As[(k0 + 1) * 68 + ACOL(k0 + 1, r)] = t1;
                As[(k0 + 2) * 68 + ACOL(k0 + 2, r)] = t2;
                As[(k0 + 3) * 68 + ACOL(k0 + 3, r)] = t3;
            }
        }
    }
    __syncthreads();

    u64 acc01[7], acc23[7];
#pragma unroll
    for (int j = 0; j < 7; j++) { acc01[j] = 0ull; acc23[j] = 0ull; }

    // GEMM phase: 32-k W chunks (fewer barriers)
    for (int kc = 0; kc < 112; kc += 32) {
        const int kspan = (kc + 32 <= 112) ? 32 : 16;
        for (int idx = tid; idx < kspan * 112; idx += 256) {
            int c = idx % 112, kk = idx / 112;
            Ws[kk][c] = W[(size_t)(kc + kk) * 112 + c];
        }
        __syncthreads();
#pragma unroll 1
        for (int kk = 0; kk < kspan; kk++) {
            int k = kc + kk;
            float4 av = *reinterpret_cast<const float4*>(&As[k * 68 + ((tr ^ (k & 15)) << 2)]);
            u64 a01, a23;
            asm("mov.b64 %0, {%1, %2};" : "=l"(a01) : "f"(av.x), "f"(av.y));
            asm("mov.b64 %0, {%1, %2};" : "=l"(a23) : "f"(av.z), "f"(av.w));
#pragma unroll
            for (int j = 0; j < 7; j++) {
                float wv = Ws[kk][tc * 7 + j];
                u64 wp;
                asm("mov.b64 %0, {%1, %1};" : "=l"(wp) : "f"(wv));
                asm("fma.rn.f32x2 %0, %1, %2, %0;" : "+l"(acc01[j]) : "l"(a01), "l"(wp));
                asm("fma.rn.f32x2 %0, %1, %2, %0;" : "+l"(acc23[j]) : "l"(a23), "l"(wp));
            }
        }
        __syncthreads();
    }

    const int r0 = row0 + tr * 4;
    float s[7], q[7];
#pragma unroll
    for (int j = 0; j < 7; j++) {
        int c = tc * 7 + j;
        float b = __ldg(&bias[c]);
        float v[4];
        asm("mov.b64 {%0, %1}, %2;" : "=f"(v[0]), "=f"(v[1]) : "l"(acc01[j]));
        asm("mov.b64 {%0, %1}, %2;" : "=f"(v[2]), "=f"(v[3]) : "l"(acc23[j]));
        float ss = 0.f, qq = 0.f;
#pragma unroll
        for (int i = 0; i < 4; i++) {
            float o = fmaxf(v[i] + b, 0.f);
            if (r0 + i < M) {
                C[(size_t)(r0 + i) * 112 + c] = o;
                ss += o;
                qq += o * o;
            }
        }
        s[j] = ss; q[j] = qq;
    }

    __syncthreads();
    float2* Ss = reinterpret_cast<float2*>(As);
#pragma unroll
    for (int j = 0; j < 7; j++)
        Ss[tr * 112 + tc * 7 + j] = make_float2(s[j], q[j]);
    __syncthreads();
    if (tid < 112) {
        float S = 0.f, Q = 0.f;
#pragma unroll
        for (int t = 0; t < 16; t++) {
            float2 p = Ss[t * 112 + tid];
            S += p.x; Q += p.y;
        }
        atomicAdd(&g_sum1[tid], (double)S);
        atomicAdd(&g_sq1[tid],  (double)Q);
    }
}

// ---------------- gemmY2 ----------------
#define SWZ(k, r) (((((r) >> 2) ^ ((k) & 15)) << 2) | ((r) & 3))
__global__ __launch_bounds__(256) void gemmY2_kernel(const float* __restrict__ H,
                                                     const float* __restrict__ W21,
                                                     const float* __restrict__ bn1g,
                                                     const float* __restrict__ bn1b,
                                                     float* __restrict__ Y2, int M) {
    __shared__ __align__(16) float Bs[112 * 64];
    __shared__ __align__(16) float W1s[112][32];
    __shared__ float a1s[FI], c1s[FI];
    const int tid = threadIdx.x;
    const int tr = tid >> 4;
    const int tc = tid & 15;
    const int row0 = blockIdx.x * 64;

    if (blockIdx.x == 0) {
        for (int i = tid; i < NG * DM; i += 256) g_pool[i] = 0.f;
        if (tid < NG) g_cnt[tid] = 0;
        if (tid < DM) { g_sum2[tid] = 0.0; g_sq2[tid] = 0.0; }
    }

    if (tid < FI) {
        double m = g_sum1[tid] / (double)NN;
        double var = g_sq1[tid] / (double)NN - m * m;
        float rs = rsqrtf((float)var + BN_EPS);
        float af = __ldg(&bn1g[tid]) * rs;
        a1s[tid] = af;
        c1s[tid] = __ldg(&bn1b[tid]) - (float)m * af;
    }
    for (int idx = tid; idx < 112 * 32; idx += 256) W1s[idx >> 5][idx & 31] = W21[idx];
    __syncthreads();

    for (int idx = tid; idx < 64 * 28; idx += 256) {
        int k4 = (idx % 28) << 2;
        int r = idx / 28;
        float4 v = make_float4(0.f, 0.f, 0.f, 0.f);
        if (row0 + r < M)
            v = *reinterpret_cast<const float4*>(H + (size_t)(row0 + r) * FI + k4);
        Bs[(k4 + 0) * 64 + SWZ(k4 + 0, r)] = v.x * a1s[k4 + 0];
        Bs[(k4 + 1) * 64 + SWZ(k4 + 1, r)] = v.y * a1s[k4 + 1];
        Bs[(k4 + 2) * 64 + SWZ(k4 + 2, r)] = v.z * a1s[k4 + 2];
        Bs[(k4 + 3) * 64 + SWZ(k4 + 3, r)] = v.w * a1s[k4 + 3];
    }
    if (tid < DM) {
        float s = 0.f;
        for (int k = 0; k < FI; k++) s += c1s[k] * W1s[k][tid];
        g_k2c[tid] = s;
    }
    __syncthreads();

    u64 z01[2], z23[2];
#pragma unroll
    for (int j = 0; j < 2; j++) { z01[j] = 0ull; z23[j] = 0ull; }
    for (int k = 0; k < 112; k++) {
        int grp = (tr ^ (k & 15)) << 2;
        float4 av = *reinterpret_cast<const float4*>(&Bs[k * 64 + grp]);
        u64 a01, a23;
        asm("mov.b64 %0, {%1, %2};" : "=l"(a01) : "f"(av.x), "f"(av.y));
        asm("mov.b64 %0, {%1, %2};" : "=l"(a23) : "f"(av.z), "f"(av.w));
        float2 wv = *reinterpret_cast<const float2*>(&W1s[k][tc * 2]);
        u64 w0, w1;
        asm("mov.b64 %0, {%1, %1};" : "=l"(w0) : "f"(wv.x));
        asm("mov.b64 %0, {%1, %1};" : "=l"(w1) : "f"(wv.y));
        asm("fma.rn.f32x2 %0, %1, %2, %0;" : "+l"(z01[0]) : "l"(a01), "l"(w0));
        asm("fma.rn.f32x2 %0, %1, %2, %0;" : "+l"(z23[0]) : "l"(a23), "l"(w0));
        asm("fma.rn.f32x2 %0, %1, %2, %0;" : "+l"(z01[1]) : "l"(a01), "l"(w1));
        asm("fma.rn.f32x2 %0, %1, %2, %0;" : "+l"(z23[1]) : "l"(a23), "l"(w1));
    }
    float v0, v1, v2, v3, u0, u1, u2, u3;
    asm("mov.b64 {%0, %1}, %2;" : "=f"(v0), "=f"(v1) : "l"(z01[0]));
    asm("mov.b64 {%0, %1}, %2;" : "=f"(v2), "=f"(v3) : "l"(z23[0]));
    asm("mov.b64 {%0, %1}, %2;" : "=f"(u0), "=f"(u1) : "l"(z01[1]));
    asm("mov.b64 {%0, %1}, %2;" : "=f"(u2), "=f"(u3) : "l"(z23[1]));
    float rr[4][2] = {{v0, u0}, {v1, u1}, {v2, u2}, {v3, u3}};
#pragma unroll
    for (int i = 0; i < 4; i++) {
        int r = row0 + tr * 4 + i;
        if (r < M)
            *reinterpret_cast<float2*>(Y2 + (size_t)r * DM + tc * 2) = make_float2(rr[i][0], rr[i][1]);
    }
}

// ---------------- fused gemmagg32 (8-deep gather ILP) ----------------
__global__ __launch_bounds__(256) void gemmagg32_kernel(const float* __restrict__ Y2,
                                                        const float* __restrict__ b21,
                                                        const float* __restrict__ W22,
                                                        const float* __restrict__ b22,
                                                        const int* __restrict__ batch, int M) {
    __shared__ __align__(16) float Zs[32 * 64];
    __shared__ __align__(16) float W2s[32][32];
    const int tid = threadIdx.x;
    const int tr = tid >> 4;
    const int tc = tid & 15;
    const int w    = tid >> 5;
    const int lane = tid & 31;
    const int row0 = blockIdx.x * 64;

    for (int idx = tid; idx < 32 * 32; idx += 256) W2s[idx >> 5][idx & 31] = W22[idx];

    float k2cv = g_k2c[lane];
    float b21v = __ldg(&b21[lane]);
#pragma unroll 1
    for (int rr = 0; rr < 8; rr++) {
        int r = w * 8 + rr;
        int gr = row0 + r;
        float acc = 0.f;
        if (gr < M) {
            int beg = __ldg(&g_rowptr[gr]);
            int end = __ldg(&g_rowptr[gr + 1]);
            acc = Y2[(size_t)gr * DM + lane];
            float a1v = 0.f, a2v = 0.f, a3v = 0.f;
            float a4v = 0.f, a5v = 0.f, a6v = 0.f, a7v = 0.f;
            int e = beg;
            for (; e + 8 <= end; e += 8) {
                int s0 = __ldg(&g_col[e + 0]);
                int s1 = __ldg(&g_col[e + 1]);
                int s2 = __ldg(&g_col[e + 2]);
                int s3 = __ldg(&g_col[e + 3]);
                int s4 = __ldg(&g_col[e + 4]);
                int s5 = __ldg(&g_col[e + 5]);
                int s6 = __ldg(&g_col[e + 6]);
                int s7 = __ldg(&g_col[e + 7]);
                acc += Y2[(size_t)s0 * DM + lane];
                a1v += Y2[(size_t)s1 * DM + lane];
                a2v += Y2[(size_t)s2 * DM + lane];
                a3v += Y2[(size_t)s3 * DM + lane];
                a4v += Y2[(size_t)s4 * DM + lane];
                a5v += Y2[(size_t)s5 * DM + lane];
                a6v += Y2[(size_t)s6 * DM + lane];
                a7v += Y2[(size_t)s7 * DM + lane];
            }
            for (; e + 4 <= end; e += 4) {
                int s0 = __ldg(&g_col[e + 0]);
                int s1 = __ldg(&g_col[e + 1]);
                int s2 = __ldg(&g_col[e + 2]);
                int s3 = __ldg(&g_col[e + 3]);
                acc += Y2[(size_t)s0 * DM + lane];
                a1v += Y2[(size_t)s1 * DM + lane];
                a2v += Y2[(size_t)s2 * DM + lane];
                a3v += Y2[(size_t)s3 * DM + lane];
            }
            for (; e < end; e++) acc += Y2[(size_t)__ldg(&g_col[e]) * DM + lane];
            float dp1 = (float)(1 + end - beg);
            acc = ((acc + a1v) + (a2v + a3v)) + ((a4v + a5v) + (a6v + a7v)) + dp1 * k2cv + b21v;
            acc = fmaxf(acc, 0.f);
        }
        Zs[lane * 64 + SWZ(lane, r)] = acc;
    }
    __syncthreads();

    u64 h01[2], h23[2];
#pragma unroll
    for (int j = 0; j < 2; j++) { h01[j] = 0ull; h23[j] = 0ull; }
#pragma unroll
    for (int k = 0; k < 32; k++) {
        int grp = (tr ^ (k & 15)) << 2;
        float4 av = *reinterpret_cast<const float4*>(&Zs[k * 64 + grp]);
        u64 a01, a23;
        asm("mov.b64 %0, {%1, %2};" : "=l"(a01) : "f"(av.x), "f"(av.y));
        asm("mov.b64 %0, {%1, %2};" : "=l"(a23) : "f"(av.z), "f"(av.w));
        float2 wv = *reinterpret_cast<const float2*>(&W2s[k][tc * 2]);
        u64 w0, w1;
        asm("mov.b64 %0, {%1, %1};" : "=l"(w0) : "f"(wv.x));
        asm("mov.b64 %0, {%1, %1};" : "=l"(w1) : "f"(wv.y));
        asm("fma.rn.f32x2 %0, %1, %2, %0;" : "+l"(h01[0]) : "l"(a01), "l"(w0));
        asm("fma.rn.f32x2 %0, %1, %2, %0;" : "+l"(h23[0]) : "l"(a23), "l"(w0));
        asm("fma.rn.f32x2 %0, %1, %2, %0;" : "+l"(h01[1]) : "l"(a01), "l"(w1));
        asm("fma.rn.f32x2 %0, %1, %2, %0;" : "+l"(h23[1]) : "l"(a23), "l"(w1));
    }

    float b0 = __ldg(&b22[tc * 2]);
    float b1v = __ldg(&b22[tc * 2 + 1]);
    float v0, v1, v2, v3, u0, u1, u2, u3;
    asm("mov.b64 {%0, %1}, %2;" : "=f"(v0), "=f"(v1) : "l"(h01[0]));
    asm("mov.b64 {%0, %1}, %2;" : "=f"(v2), "=f"(v3) : "l"(h23[0]));
    asm("mov.b64 {%0, %1}, %2;" : "=f"(u0), "=f"(u1) : "l"(h01[1]));
    asm("mov.b64 {%0, %1}, %2;" : "=f"(u2), "=f"(u3) : "l"(h23[1]));
    float rr[4][2] = {{v0, u0}, {v1, u1}, {v2, u2}, {v3, u3}};

    float s0 = 0.f, q0 = 0.f, s1 = 0.f, q1 = 0.f;
#pragma unroll
    for (int i = 0; i < 4; i++) {
        int r = row0 + tr * 4 + i;
        float o0 = fmaxf(rr[i][0] + b0, 0.f);
        float o1 = fmaxf(rr[i][1] + b1v, 0.f);
        rr[i][0] = o0; rr[i][1] = o1;
        if (r < M) {
            s0 += o0; q0 += o0 * o0;
            s1 += o1; q1 += o1 * o1;
        }
    }

    __syncthreads();
    float2* part = reinterpret_cast<float2*>(Zs);
    part[tr * 32 + tc * 2]     = make_float2(s0, q0);
    part[tr * 32 + tc * 2 + 1] = make_float2(s1, q1);
    __syncthreads();
    if (tid < 32) {
        float S = 0.f, Q = 0.f;
#pragma unroll
        for (int t = 0; t < 16; t++) {
            float2 p = part[t * 32 + tid];
            S += p.x; Q += p.y;
        }
        atomicAdd(&g_sum2[tid], (double)S);
        atomicAdd(&g_sq2[tid],  (double)Q);
    }

#pragma unroll
    for (int i = 0; i < 4; i++) {
        int r = row0 + tr * 4 + i;
        if (r < M) {
            int b = __ldg(&batch[r]);
            atomicAdd(&g_pool[b * DM + tc * 2],     rr[i][0]);
            atomicAdd(&g_pool[b * DM + tc * 2 + 1], rr[i][1]);
            if (tc == 0) atomicAdd(&g_cnt[b], 1);
        }
    }
}

// ---------------- dense head ----------------
__global__ void head_kernel(const float* __restrict__ bn2g, const float* __restrict__ bn2b,
                            const float* __restrict__ fcxd_w, const float* __restrict__ fcxd_b,
                            const float* __restrict__ fc1_w,  const float* __restrict__ fc1_b,
                            const float* __restrict__ fc2_w,  const float* __restrict__ fc2_b,
                            const float* __restrict__ fc3_w,  const float* __restrict__ fc3_b,
                            const float* __restrict__ fc4_w,  const float* __restrict__ fc4_b,
                            const float* __restrict__ fc5_w,  const float* __restrict__ fc5_b,
                            float* __restrict__ out) {
    __shared__ float p[DM], z1[64], z2[32], z3[16], z4[8], z5[2];
    int g = blockIdx.x, t = threadIdx.x;
    if (t < DM) {
        double m = g_sum2[t] / (double)NN;
        double var = g_sq2[t] / (double)NN - m * m;
        float rs = rsqrtf((float)var + BN_EPS);
        float af = __ldg(&bn2g[t]) * rs;
        float cf = __ldg(&bn2b[t]) - (float)m * af;
        float cnt = (float)g_cnt[g];
        p[t] = af * g_pool[g * DM + t] + cnt * cf;
    }
    __syncthreads();
    if (t < 64) {
        float s = fcxd_b[t];
        for (int k = 0; k < 32; k++) s += p[k] * fcxd_w[k * 64 + t];
        z1[t] = fmaxf(s, 0.0f);
    }
    __syncthreads();
    if (t < 32) {
        float s = fc1_b[t];
        for (int k = 0; k < 64; k++) s += z1[k] * fc1_w[k * 32 + t];
        z2[t] = s;
    }
    __syncthreads();
    if (t < 16) {
        float s = fc2_b[t];
        for (int k = 0; k < 32; k++) s += z2[k] * fc2_w[k * 16 + t];
        z3[t] = s;
    }
    __syncthreads();
    if (t < 8) {
        float s = fc3_b[t];
        for (int k = 0; k < 16; k++) s += z3[k] * fc3_w[k * 8 + t];
        z4[t] = s;
    }
    __syncthreads();
    if (t < 2) {
        float s = fc4_b[t];
        for (int k = 0; k < 8; k++) s += z4[k] * fc4_w[k * 2 + t];
        z5[t] = s;
    }
    __syncthreads();
    if (t == 0) out[g] = z5[0] * fc5_w[0] + z5[1] * fc5_w[1] + fc5_b[0];
}

// ---------------- launch ----------------
extern "C" void kernel_launch(void* const* d_in, const int* in_sizes, int n_in,
                              void* d_out, int out_size) {
    const float* x      = (const float*)d_in[0];
    const int*   src    = (const int*)d_in[1];
    const int*   dst    = (const int*)d_in[2];
    const int*   batch  = (const int*)d_in[3];
    const float* g1_w1  = (const float*)d_in[4];
    const float* g1_b1  = (const float*)d_in[5];
    const float* g1_w2  = (const float*)d_in[6];
    const float* g1_b2  = (const float*)d_in[7];
    const float* bn1_g  = (const float*)d_in[8];
    const float* bn1_b  = (const float*)d_in[9];
    const float* g2_w1  = (const float*)d_in[10];
    const float* g2_b1  = (const float*)d_in[11];
    const float* g2_w2  = (const float*)d_in[12];
    const float* g2_b2  = (const float*)d_in[13];
    const float* bn2_g  = (const float*)d_in[14];
    const float* bn2_b  = (const float*)d_in[15];
    const float* fcxd_w = (const float*)d_in[16];
    const float* fcxd_b = (const float*)d_in[17];
    const float* fc1_w  = (const float*)d_in[18];
    const float* fc1_b  = (const float*)d_in[19];
    const float* fc2_w  = (const float*)d_in[20];
    const float* fc2_b  = (const float*)d_in[21];
    const float* fc3_w  = (const float*)d_in[22];
    const float* fc3_b  = (const float*)d_in[23];
    const float* fc4_w  = (const float*)d_in[24];
    const float* fc4_b  = (const float*)d_in[25];
    const float* fc5_w  = (const float*)d_in[26];
    const float* fc5_b  = (const float*)d_in[27];
    float* out = (float*)d_out;

    const int E = in_sizes[1];
    const int M = NN;

    float *Y1, *H, *Y2;
    cudaGetSymbolAddress((void**)&Y1, g_Y1);
    cudaGetSymbolAddress((void**)&H,  g_H);
    cudaGetSymbolAddress((void**)&Y2, g_Y2);

    static cudaStream_t s_side = nullptr;
    static cudaEvent_t ev_fork = nullptr, ev_join = nullptr;
    if (s_side == nullptr) {
        cudaStreamCreateWithFlags(&s_side, cudaStreamNonBlocking);
        cudaEventCreateWithFlags(&ev_fork, cudaEventDisableTiming);
        cudaEventCreateWithFlags(&ev_join, cudaEventDisableTiming);
    }

    // fork side stream (CSR build)
    cudaEventRecord(ev_fork, 0);
    cudaStreamWaitEvent(s_side, ev_fork, 0);
    hist_kernel<<<(E + 255) / 256, 256, 0, s_side>>>(dst, E);
    scanA_kernel<<<SCAN_NBLK, SCAN_BLK, 0, s_side>>>();
    scanC_kernel<<<SCAN_NBLK, SCAN_BLK, 0, s_side>>>();

    // main: Y1 = x @ W11 (zeroes stats1)
    gemm112_kernel<<<(M + 127) / 128, 256>>>(x, g1_w1, Y1, M);

    fill_kernel<<<(E + 255) / 256, 256, 0, s_side>>>(src, dst, E);
    cudaEventRecord(ev_join, s_side);
    cudaStreamWaitEvent(0, ev_join, 0);

    // fused layer-1 tail
    aggGemm112_kernel<<<(M + 63) / 64, 256>>>(Y1, g1_b1, g1_w2, g1_b2, H, M);

    // layer 2
    gemmY2_kernel<<<(M + 63) / 64, 256>>>(H, g2_w1, bn1_g, bn1_b, Y2, M);
    gemmagg32_kernel<<<(M + 63) / 64, 256>>>(Y2, g2_b1, g2_w2, g2_b2, batch, M);

    // head
    head_kernel<<<NG, 64>>>(bn2_g, bn2_b, fcxd_w, fcxd_b, fc1_w, fc1_b, fc2_w, fc2_b,
                            fc3_w, fc3_b, fc4_w, fc4_b, fc5_w, fc5_b, out);
}

// round 17
// speedup vs baseline: 1.1922x; 1.1922x over previous
#include <cuda_runtime.h>
#include <cuda_bf16.h>
#include <cuda_fp16.h>
#include <cstdint>

#define NN 50000
#define NE 800000
#define FI 112
#define DM 32
#define NG 256
#define BN_EPS 1e-5f
#define SCAN_BLK 1024
#define SCAN_NBLK ((NN + SCAN_BLK - 1) / SCAN_BLK)   // 49

typedef unsigned long long u64;

// ---------------- device scratch ----------------
__device__ __half  g_Y1h[NN * FI];   // Y1 = x @ W11 (fp16 storage)
__device__ float   g_H [NN * FI];
__device__ float   g_Y2[NN * DM];
__device__ double  g_sum1[FI], g_sq1[FI];
__device__ double  g_sum2[DM], g_sq2[DM];
__device__ float   g_k2c[DM];
__device__ float   g_pool[NG * DM];
__device__ int     g_cnt[NG];
__device__ int     g_deg[NN];          // zero-init at load; consume-reset by scanA
__device__ int     g_rowptr[NN + 1];
__device__ int     g_cursor[NN];
__device__ int     g_col[NE];
__device__ int     g_blocksum[SCAN_NBLK];

// ---------------- CSR build ----------------
__global__ void hist_kernel(const int* __restrict__ dst, int E) {
    int e = blockIdx.x * blockDim.x + threadIdx.x;
    if (e < E) atomicAdd(&g_deg[dst[e]], 1);
}

__global__ __launch_bounds__(SCAN_BLK) void scanA_kernel() {
    __shared__ int wsum[32];
    int t = threadIdx.x;
    int idx = blockIdx.x * SCAN_BLK + t;
    int v = 0;
    if (idx < NN) {
        v = g_deg[idx];
        g_deg[idx] = 0;
    }
    int lane = t & 31, wid = t >> 5;
    int p = v;
#pragma unroll
    for (int d = 1; d < 32; d <<= 1) {
        int n = __shfl_up_sync(0xffffffffu, p, d);
        if (lane >= d) p += n;
    }
    if (lane == 31) wsum[wid] = p;
    __syncthreads();
    if (wid == 0) {
        int w = wsum[lane];
#pragma unroll
        for (int d = 1; d < 32; d <<= 1) {
            int n = __shfl_up_sync(0xffffffffu, w, d);
            if (lane >= d) w += n;
        }
        wsum[lane] = w;
    }
    __syncthreads();
    int excl = (p - v) + (wid ? wsum[wid - 1] : 0);
    if (idx < NN) g_rowptr[idx] = excl;
    if (t == SCAN_BLK - 1) g_blocksum[blockIdx.x] = excl + v;
}

__global__ __launch_bounds__(SCAN_BLK) void scanC_kernel() {
    __shared__ int es[SCAN_NBLK + 1];
    int t = threadIdx.x;
    if (t == 0) {
        int run = 0;
#pragma unroll 1
        for (int i = 0; i < SCAN_NBLK; i++) {
            es[i] = run;
            run += g_blocksum[i];
        }
        es[SCAN_NBLK] = run;
    }
    __syncthreads();
    int idx = blockIdx.x * SCAN_BLK + t;
    if (idx < NN) {
        int r = g_rowptr[idx] + es[blockIdx.x];
        g_rowptr[idx] = r;
        g_cursor[idx] = r;
    }
    if (blockIdx.x == SCAN_NBLK - 1 && t == 0)
        g_rowptr[NN] = es[SCAN_NBLK];
}

__global__ void fill_kernel(const int* __restrict__ src, const int* __restrict__ dst, int E) {
    int e = blockIdx.x * blockDim.x + threadIdx.x;
    if (e < E) {
        int p = atomicAdd(&g_cursor[dst[e]], 1);
        g_col[p] = src[e];
    }
}

// ---------------- gemm112: Y1h = fp16(x @ W11), 128-row tiles (R11 layout) ----------------
__global__ __launch_bounds__(256) void gemm112_kernel(const float* __restrict__ A,
                                                      const float* __restrict__ W,
                                                      __half* __restrict__ C, int M) {
    __shared__ __align__(16) float As[16][132];
    __shared__ __align__(16) float Ws[16][112];
    const int tid = threadIdx.x;
    const int tr = tid >> 4;
    const int tc = tid & 15;
    const int row0 = blockIdx.x * 128;

    if (blockIdx.x == 0 && tid < FI) { g_sum1[tid] = 0.0; g_sq1[tid] = 0.0; }

    u64 acc01[7], acc23[7], acc45[7], acc67[7];
#pragma unroll
    for (int j = 0; j < 7; j++) { acc01[j] = 0ull; acc23[j] = 0ull; acc45[j] = 0ull; acc67[j] = 0ull; }

    for (int kc = 0; kc < 112; kc += 16) {
#pragma unroll
        for (int i = 0; i < 2; i++) {
            int idx = tid + i * 256;
            int r = idx >> 2;
            int kq = (idx & 3) << 2;
            float4 v = make_float4(0.f, 0.f, 0.f, 0.f);
            if (row0 + r < M)
                v = *reinterpret_cast<const float4*>(A + (size_t)(row0 + r) * FI + kc + kq);
            As[kq + 0][r] = v.x;
            As[kq + 1][r] = v.y;
            As[kq + 2][r] = v.z;
            As[kq + 3][r] = v.w;
        }
#pragma unroll
        for (int i = 0; i < 7; i++) {
            int idx = tid + i * 256;
            int c = idx % 112, kk = idx / 112;
            Ws[kk][c] = W[(size_t)(kc + kk) * 112 + c];
        }
        __syncthreads();
#pragma unroll
        for (int kk = 0; kk < 16; kk++) {
            float4 alo = *reinterpret_cast<const float4*>(&As[kk][tr * 8]);
            float4 ahi = *reinterpret_cast<const float4*>(&As[kk][tr * 8 + 4]);
            u64 a01, a23, a45, a67;
            asm("mov.b64 %0, {%1, %2};" : "=l"(a01) : "f"(alo.x), "f"(alo.y));
            asm("mov.b64 %0, {%1, %2};" : "=l"(a23) : "f"(alo.z), "f"(alo.w));
            asm("mov.b64 %0, {%1, %2};" : "=l"(a45) : "f"(ahi.x), "f"(ahi.y));
            asm("mov.b64 %0, {%1, %2};" : "=l"(a67) : "f"(ahi.z), "f"(ahi.w));
#pragma unroll
            for (int j = 0; j < 7; j++) {
                float wv = Ws[kk][tc * 7 + j];
                u64 wp;
                asm("mov.b64 %0, {%1, %1};" : "=l"(wp) : "f"(wv));
                asm("fma.rn.f32x2 %0, %1, %2, %0;" : "+l"(acc01[j]) : "l"(a01), "l"(wp));
                asm("fma.rn.f32x2 %0, %1, %2, %0;" : "+l"(acc23[j]) : "l"(a23), "l"(wp));
                asm("fma.rn.f32x2 %0, %1, %2, %0;" : "+l"(acc45[j]) : "l"(a45), "l"(wp));
                asm("fma.rn.f32x2 %0, %1, %2, %0;" : "+l"(acc67[j]) : "l"(a67), "l"(wp));
            }
        }
        __syncthreads();
    }

    const int r0 = row0 + tr * 8;
#pragma unroll
    for (int j = 0; j < 7; j++) {
        int c = tc * 7 + j;
        float v[8];
        asm("mov.b64 {%0, %1}, %2;" : "=f"(v[0]), "=f"(v[1]) : "l"(acc01[j]));
        asm("mov.b64 {%0, %1}, %2;" : "=f"(v[2]), "=f"(v[3]) : "l"(acc23[j]));
        asm("mov.b64 {%0, %1}, %2;" : "=f"(v[4]), "=f"(v[5]) : "l"(acc45[j]));
        asm("mov.b64 {%0, %1}, %2;" : "=f"(v[6]), "=f"(v[7]) : "l"(acc67[j]));
#pragma unroll
        for (int i = 0; i < 8; i++)
            if (r0 + i < M) C[(size_t)(r0 + i) * 112 + c] = __float2half(v[i]);
    }
}

// ---------------- fused aggGemm112: fp16 gather (half L2 traffic) + full-K GEMM (R11 layout) ----------------
#define ACOL(k, r) (((((r) >> 2) ^ ((k) & 15)) << 2) | ((r) & 3))
__device__ __forceinline__ void h4_acc(uint2 u, float4& a) {
    float2 lo = __half22float2(*reinterpret_cast<__half2*>(&u.x));
    float2 hi = __half22float2(*reinterpret_cast<__half2*>(&u.y));
    a.x += lo.x; a.y += lo.y; a.z += hi.x; a.w += hi.y;
}
__global__ __launch_bounds__(256) void aggGemm112_kernel(const __half* __restrict__ Yh,
                                                         const float* __restrict__ b1,
                                                         const float* __restrict__ W,
                                                         const float* __restrict__ bias,
                                                         float* __restrict__ C, int M) {
    __shared__ __align__(16) float As[112 * 68];
    __shared__ __align__(16) float Ws[16][112];
    const int tid = threadIdx.x;
    const int tr = tid >> 4;
    const int tc = tid & 15;
    const int w    = tid >> 5;
    const int lane = tid & 31;
    const int row0 = blockIdx.x * 64;

    {
        bool act = lane < 28;
        size_t foff = (size_t)(lane << 2);
        float4 bia = make_float4(0.f, 0.f, 0.f, 0.f);
        if (act) bia = *reinterpret_cast<const float4*>(b1 + foff);
#pragma unroll 1
        for (int rr = 0; rr < 8; rr++) {
            int r = w * 8 + rr;
            int gr = row0 + r;
            float4 acc  = make_float4(0.f, 0.f, 0.f, 0.f);
            float4 acc1 = acc, acc2 = acc, acc3 = acc;
            if (gr < M) {
                int beg = __ldg(&g_rowptr[gr]);
                int end = __ldg(&g_rowptr[gr + 1]);
                if (act) {
                    uint2 u = *reinterpret_cast<const uint2*>(Yh + (size_t)gr * FI + foff);
                    h4_acc(u, acc);
                }
                int e = beg;
                for (; e + 8 <= end; e += 8) {
                    int s0 = __ldg(&g_col[e + 0]);
                    int s1 = __ldg(&g_col[e + 1]);
                    int s2 = __ldg(&g_col[e + 2]);
                    int s3 = __ldg(&g_col[e + 3]);
                    int s4 = __ldg(&g_col[e + 4]);
                    int s5 = __ldg(&g_col[e + 5]);
                    int s6 = __ldg(&g_col[e + 6]);
                    int s7 = __ldg(&g_col[e + 7]);
                    if (act) {
                        uint2 u0 = *reinterpret_cast<const uint2*>(Yh + (size_t)s0 * FI + foff);
                        uint2 u1 = *reinterpret_cast<const uint2*>(Yh + (size_t)s1 * FI + foff);
                        uint2 u2 = *reinterpret_cast<const uint2*>(Yh + (size_t)s2 * FI + foff);
                        uint2 u3 = *reinterpret_cast<const uint2*>(Yh + (size_t)s3 * FI + foff);
                        uint2 u4 = *reinterpret_cast<const uint2*>(Yh + (size_t)s4 * FI + foff);
                        uint2 u5 = *reinterpret_cast<const uint2*>(Yh + (size_t)s5 * FI + foff);
                        uint2 u6 = *reinterpret_cast<const uint2*>(Yh + (size_t)s6 * FI + foff);
                        uint2 u7 = *reinterpret_cast<const uint2*>(Yh + (size_t)s7 * FI + foff);
                        h4_acc(u0, acc);  h4_acc(u4, acc);
                        h4_acc(u1, acc1); h4_acc(u5, acc1);
                        h4_acc(u2, acc2); h4_acc(u6, acc2);
                        h4_acc(u3, acc3); h4_acc(u7, acc3);
                    }
                }
                for (; e + 4 <= end; e += 4) {
                    int s0 = __ldg(&g_col[e + 0]);
                    int s1 = __ldg(&g_col[e + 1]);
                    int s2 = __ldg(&g_col[e + 2]);
                    int s3 = __ldg(&g_col[e + 3]);
                    if (act) {
                        uint2 u0 = *reinterpret_cast<const uint2*>(Yh + (size_t)s0 * FI + foff);
                        uint2 u1 = *reinterpret_cast<const uint2*>(Yh + (size_t)s1 * FI + foff);
                        uint2 u2 = *reinterpret_cast<const uint2*>(Yh + (size_t)s2 * FI + foff);
                        uint2 u3 = *reinterpret_cast<const uint2*>(Yh + (size_t)s3 * FI + foff);
                        h4_acc(u0, acc);
                        h4_acc(u1, acc1);
                        h4_acc(u2, acc2);
                        h4_acc(u3, acc3);
                    }
                }
                for (; e < end; e++) {
                    int s = __ldg(&g_col[e]);
                    if (act) {
                        uint2 u = *reinterpret_cast<const uint2*>(Yh + (size_t)s * FI + foff);
                        h4_acc(u, acc);
                    }
                }
            }
            if (act) {
                float t0 = fmaxf((acc.x + acc1.x) + (acc2.x + acc3.x) + bia.x, 0.f);
                float t1 = fmaxf((acc.y + acc1.y) + (acc2.y + acc3.y) + bia.y, 0.f);
                float t2 = fmaxf((acc.z + acc1.z) + (acc2.z + acc3.z) + bia.z, 0.f);
                float t3 = fmaxf((acc.w + acc1.w) + (acc2.w + acc3.w) + bia.w, 0.f);
                int k0 = lane << 2;
                As[(k0 + 0) * 68 + ACOL(k0 + 0, r)] = t0;
                As[(k0 + 1) * 68 + ACOL(k0 + 1, r)] = t1;
                As[(k0 + 2) * 68 + ACOL(k0 + 2, r)] = t2;
                As[(k0 + 3) * 68 + ACOL(k0 + 3, r)] = t3;
            }
        }
    }
    __syncthreads();

    u64 acc01[7], acc23[7];
#pragma unroll
    for (int j = 0; j < 7; j++) { acc01[j] = 0ull; acc23[j] = 0ull; }

    for (int kc = 0; kc < 112; kc += 16) {
#pragma unroll
        for (int i = 0; i < 7; i++) {
            int idx = tid + i * 256;
            int c = idx % 112, kk = idx / 112;
            Ws[kk][c] = W[(size_t)(kc + kk) * 112 + c];
        }
        __syncthreads();
#pragma unroll
        for (int kk = 0; kk < 16; kk++) {
            int k = kc + kk;
            float4 av = *reinterpret_cast<const float4*>(&As[k * 68 + ((tr ^ (k & 15)) << 2)]);
            u64 a01, a23;
            asm("mov.b64 %0, {%1, %2};" : "=l"(a01) : "f"(av.x), "f"(av.y));
            asm("mov.b64 %0, {%1, %2};" : "=l"(a23) : "f"(av.z), "f"(av.w));
#pragma unroll
            for (int j = 0; j < 7; j++) {
                float wv = Ws[kk][tc * 7 + j];
                u64 wp;
                asm("mov.b64 %0, {%1, %1};" : "=l"(wp) : "f"(wv));
                asm("fma.rn.f32x2 %0, %1, %2, %0;" : "+l"(acc01[j]) : "l"(a01), "l"(wp));
                asm("fma.rn.f32x2 %0, %1, %2, %0;" : "+l"(acc23[j]) : "l"(a23), "l"(wp));
            }
        }
        __syncthreads();
    }

    const int r0 = row0 + tr * 4;
    float s[7], q[7];
#pragma unroll
    for (int j = 0; j < 7; j++) {
        int c = tc * 7 + j;
        float b = __ldg(&bias[c]);
        float v[4];
        asm("mov.b64 {%0, %1}, %2;" : "=f"(v[0]), "=f"(v[1]) : "l"(acc01[j]));
        asm("mov.b64 {%0, %1}, %2;" : "=f"(v[2]), "=f"(v[3]) : "l"(acc23[j]));
        float ss = 0.f, qq = 0.f;
#pragma unroll
        for (int i = 0; i < 4; i++) {
            float o = fmaxf(v[i] + b, 0.f);
            if (r0 + i < M) {
                C[(size_t)(r0 + i) * 112 + c] = o;
                ss += o;
                qq += o * o;
            }
        }
        s[j] = ss; q[j] = qq;
    }

    __syncthreads();
    float2* Ss = reinterpret_cast<float2*>(As);
#pragma unroll
    for (int j = 0; j < 7; j++)
        Ss[tr * 112 + tc * 7 + j] = make_float2(s[j], q[j]);
    __syncthreads();
    if (tid < 112) {
        float S = 0.f, Q = 0.f;
#pragma unroll
        for (int t = 0; t < 16; t++) {
            float2 p = Ss[t * 112 + tid];
            S += p.x; Q += p.y;
        }
        atomicAdd(&g_sum1[tid], (double)S);
        atomicAdd(&g_sq1[tid],  (double)Q);
    }
}

// ---------------- gemmY2 (R11) ----------------
#define SWZ(k, r) (((((r) >> 2) ^ ((k) & 15)) << 2) | ((r) & 3))
__global__ __launch_bounds__(256) void gemmY2_kernel(const float* __restrict__ H,
                                                     const float* __restrict__ W21,
                                                     const float* __restrict__ bn1g,
                                                     const float* __restrict__ bn1b,
                                                     float* __restrict__ Y2, int M) {
    __shared__ __align__(16) float Bs[112 * 64];
    __shared__ __align__(16) float W1s[112][32];
    __shared__ float a1s[FI], c1s[FI];
    const int tid = threadIdx.x;
    const int tr = tid >> 4;
    const int tc = tid & 15;
    const int row0 = blockIdx.x * 64;

    if (blockIdx.x == 0) {
        for (int i = tid; i < NG * DM; i += 256) g_pool[i] = 0.f;
        if (tid < NG) g_cnt[tid] = 0;
        if (tid < DM) { g_sum2[tid] = 0.0; g_sq2[tid] = 0.0; }
    }

    if (tid < FI) {
        double m = g_sum1[tid] / (double)NN;
        double var = g_sq1[tid] / (double)NN - m * m;
        float rs = rsqrtf((float)var + BN_EPS);
        float af = __ldg(&bn1g[tid]) * rs;
        a1s[tid] = af;
        c1s[tid] = __ldg(&bn1b[tid]) - (float)m * af;
    }
    for (int idx = tid; idx < 112 * 32; idx += 256) W1s[idx >> 5][idx & 31] = W21[idx];
    __syncthreads();

    for (int idx = tid; idx < 64 * 28; idx += 256) {
        int k4 = (idx % 28) << 2;
        int r = idx / 28;
        float4 v = make_float4(0.f, 0.f, 0.f, 0.f);
        if (row0 + r < M)
            v = *reinterpret_cast<const float4*>(H + (size_t)(row0 + r) * FI + k4);
        Bs[(k4 + 0) * 64 + SWZ(k4 + 0, r)] = v.x * a1s[k4 + 0];
        Bs[(k4 + 1) * 64 + SWZ(k4 + 1, r)] = v.y * a1s[k4 + 1];
        Bs[(k4 + 2) * 64 + SWZ(k4 + 2, r)] = v.z * a1s[k4 + 2];
        Bs[(k4 + 3) * 64 + SWZ(k4 + 3, r)] = v.w * a1s[k4 + 3];
    }
    if (tid < DM) {
        float s = 0.f;
        for (int k = 0; k < FI; k++) s += c1s[k] * W1s[k][tid];
        g_k2c[tid] = s;
    }
    __syncthreads();

    u64 z01[2], z23[2];
#pragma unroll
    for (int j = 0; j < 2; j++) { z01[j] = 0ull; z23[j] = 0ull; }
    for (int k = 0; k < 112; k++) {
        int grp = (tr ^ (k & 15)) << 2;
        float4 av = *reinterpret_cast<const float4*>(&Bs[k * 64 + grp]);
        u64 a01, a23;
        asm("mov.b64 %0, {%1, %2};" : "=l"(a01) : "f"(av.x), "f"(av.y));
        asm("mov.b64 %0, {%1, %2};" : "=l"(a23) : "f"(av.z), "f"(av.w));
        float2 wv = *reinterpret_cast<const float2*>(&W1s[k][tc * 2]);
        u64 w0, w1;
        asm("mov.b64 %0, {%1, %1};" : "=l"(w0) : "f"(wv.x));
        asm("mov.b64 %0, {%1, %1};" : "=l"(w1) : "f"(wv.y));
        asm("fma.rn.f32x2 %0, %1, %2, %0;" : "+l"(z01[0]) : "l"(a01), "l"(w0));
        asm("fma.rn.f32x2 %0, %1, %2, %0;" : "+l"(z23[0]) : "l"(a23), "l"(w0));
        asm("fma.rn.f32x2 %0, %1, %2, %0;" : "+l"(z01[1]) : "l"(a01), "l"(w1));
        asm("fma.rn.f32x2 %0, %1, %2, %0;" : "+l"(z23[1]) : "l"(a23), "l"(w1));
    }
    float v0, v1, v2, v3, u0, u1, u2, u3;
    asm("mov.b64 {%0, %1}, %2;" : "=f"(v0), "=f"(v1) : "l"(z01[0]));
    asm("mov.b64 {%0, %1}, %2;" : "=f"(v2), "=f"(v3) : "l"(z23[0]));
    asm("mov.b64 {%0, %1}, %2;" : "=f"(u0), "=f"(u1) : "l"(z01[1]));
    asm("mov.b64 {%0, %1}, %2;" : "=f"(u2), "=f"(u3) : "l"(z23[1]));
    float rr[4][2] = {{v0, u0}, {v1, u1}, {v2, u2}, {v3, u3}};
#pragma unroll
    for (int i = 0; i < 4; i++) {
        int r = row0 + tr * 4 + i;
        if (r < M)
            *reinterpret_cast<float2*>(Y2 + (size_t)r * DM + tc * 2) = make_float2(rr[i][0], rr[i][1]);
    }
}

// ---------------- fused gemmagg32 (R11: 4-deep gather) ----------------
__global__ __launch_bounds__(256) void gemmagg32_kernel(const float* __restrict__ Y2,
                                                        const float* __restrict__ b21,
                                                        const float* __restrict__ W22,
                                                        const float* __restrict__ b22,
                                                        const int* __restrict__ batch, int M) {
    __shared__ __align__(16) float Zs[32 * 64];
    __shared__ __align__(16) float W2s[32][32];
    const int tid = threadIdx.x;
    const int tr = tid >> 4;
    const int tc = tid & 15;
    const int w    = tid >> 5;
    const int lane = tid & 31;
    const int row0 = blockIdx.x * 64;

    for (int idx = tid; idx < 32 * 32; idx += 256) W2s[idx >> 5][idx & 31] = W22[idx];

    float k2cv = g_k2c[lane];
    float b21v = __ldg(&b21[lane]);
#pragma unroll 1
    for (int rr = 0; rr < 8; rr++) {
        int r = w * 8 + rr;
        int gr = row0 + r;
        float acc = 0.f;
        if (gr < M) {
            int beg = __ldg(&g_rowptr[gr]);
            int end = __ldg(&g_rowptr[gr + 1]);
            acc = Y2[(size_t)gr * DM + lane];
            float a1v = 0.f, a2v = 0.f, a3v = 0.f;
            int e = beg;
            for (; e + 4 <= end; e += 4) {
                int s0 = __ldg(&g_col[e + 0]);
                int s1 = __ldg(&g_col[e + 1]);
                int s2 = __ldg(&g_col[e + 2]);
                int s3 = __ldg(&g_col[e + 3]);
                acc += Y2[(size_t)s0 * DM + lane];
                a1v += Y2[(size_t)s1 * DM + lane];
                a2v += Y2[(size_t)s2 * DM + lane];
                a3v += Y2[(size_t)s3 * DM + lane];
            }
            for (; e < end; e++) acc += Y2[(size_t)__ldg(&g_col[e]) * DM + lane];
            float dp1 = (float)(1 + end - beg);
            acc = fmaxf((acc + a1v) + (a2v + a3v) + dp1 * k2cv + b21v, 0.f);
        }
        Zs[lane * 64 + SWZ(lane, r)] = acc;
    }
    __syncthreads();

    u64 h01[2], h23[2];
#pragma unroll
    for (int j = 0; j < 2; j++) { h01[j] = 0ull; h23[j] = 0ull; }
#pragma unroll
    for (int k = 0; k < 32; k++) {
        int grp = (tr ^ (k & 15)) << 2;
        float4 av = *reinterpret_cast<const float4*>(&Zs[k * 64 + grp]);
        u64 a01, a23;
        asm("mov.b64 %0, {%1, %2};" : "=l"(a01) : "f"(av.x), "f"(av.y));
        asm("mov.b64 %0, {%1, %2};" : "=l"(a23) : "f"(av.z), "f"(av.w));
        float2 wv = *reinterpret_cast<const float2*>(&W2s[k][tc * 2]);
        u64 w0, w1;
        asm("mov.b64 %0, {%1, %1};" : "=l"(w0) : "f"(wv.x));
        asm("mov.b64 %0, {%1, %1};" : "=l"(w1) : "f"(wv.y));
        asm("fma.rn.f32x2 %0, %1, %2, %0;" : "+l"(h01[0]) : "l"(a01), "l"(w0));
        asm("fma.rn.f32x2 %0, %1, %2, %0;" : "+l"(h23[0]) : "l"(a23), "l"(w0));
        asm("fma.rn.f32x2 %0, %1, %2, %0;" : "+l"(h01[1]) : "l"(a01), "l"(w1));
        asm("fma.rn.f32x2 %0, %1, %2, %0;" : "+l"(h23[1]) : "l"(a23), "l"(w1));
    }

    float b0 = __ldg(&b22[tc * 2]);
    float b1v = __ldg(&b22[tc * 2 + 1]);
    float v0, v1, v2, v3, u0, u1, u2, u3;
    asm("mov.b64 {%0, %1}, %2;" : "=f"(v0), "=f"(v1) : "l"(h01[0]));
    asm("mov.b64 {%0, %1}, %2;" : "=f"(v2), "=f"(v3) : "l"(h23[0]));
    asm("mov.b64 {%0, %1}, %2;" : "=f"(u0), "=f"(u1) : "l"(h01[1]));
    asm("mov.b64 {%0, %1}, %2;" : "=f"(u2), "=f"(u3) : "l"(h23[1]));
    float rr[4][2] = {{v0, u0}, {v1, u1}, {v2, u2}, {v3, u3}};

    float s0 = 0.f, q0 = 0.f, s1 = 0.f, q1 = 0.f;
#pragma unroll
    for (int i = 0; i < 4; i++) {
        int r = row0 + tr * 4 + i;
        float o0 = fmaxf(rr[i][0] + b0, 0.f);
        float o1 = fmaxf(rr[i][1] + b1v, 0.f);
        rr[i][0] = o0; rr[i][1] = o1;
        if (r < M) {
            s0 += o0; q0 += o0 * o0;
            s1 += o1; q1 += o1 * o1;
        }
    }

    __syncthreads();
    float2* part = reinterpret_cast<float2*>(Zs);
    part[tr * 32 + tc * 2]     = make_float2(s0, q0);
    part[tr * 32 + tc * 2 + 1] = make_float2(s1, q1);
    __syncthreads();
    if (tid < 32) {
        float S = 0.f, Q = 0.f;
#pragma unroll
        for (int t = 0; t < 16; t++) {
            float2 p = part[t * 32 + tid];
            S += p.x; Q += p.y;
        }
        atomicAdd(&g_sum2[tid], (double)S);
        atomicAdd(&g_sq2[tid],  (double)Q);
    }

#pragma unroll
    for (int i = 0; i < 4; i++) {
        int r = row0 + tr * 4 + i;
        if (r < M) {
            int b = __ldg(&batch[r]);
            atomicAdd(&g_pool[b * DM + tc * 2],     rr[i][0]);
            atomicAdd(&g_pool[b * DM + tc * 2 + 1], rr[i][1]);
            if (tc == 0) atomicAdd(&g_cnt[b], 1);
        }
    }
}

// ---------------- dense head ----------------
__global__ void head_kernel(const float* __restrict__ bn2g, const float* __restrict__ bn2b,
                            const float* __restrict__ fcxd_w, const float* __restrict__ fcxd_b,
                            const float* __restrict__ fc1_w,  const float* __restrict__ fc1_b,
                            const float* __restrict__ fc2_w,  const float* __restrict__ fc2_b,
                            const float* __restrict__ fc3_w,  const float* __restrict__ fc3_b,
                            const float* __restrict__ fc4_w,  const float* __restrict__ fc4_b,
                            const float* __restrict__ fc5_w,  const float* __restrict__ fc5_b,
                            float* __restrict__ out) {
    __shared__ float p[DM], z1[64], z2[32], z3[16], z4[8], z5[2];
    int g = blockIdx.x, t = threadIdx.x;
    if (t < DM) {
        double m = g_sum2[t] / (double)NN;
        double var = g_sq2[t] / (double)NN - m * m;
        float rs = rsqrtf((float)var + BN_EPS);
        float af = __ldg(&bn2g[t]) * rs;
        float cf = __ldg(&bn2b[t]) - (float)m * af;
        float cnt = (float)g_cnt[g];
        p[t] = af * g_pool[g * DM + t] + cnt * cf;
    }
    __syncthreads();
    if (t < 64) {
        float s = fcxd_b[t];
        for (int k = 0; k < 32; k++) s += p[k] * fcxd_w[k * 64 + t];
        z1[t] = fmaxf(s, 0.0f);
    }
    __syncthreads();
    if (t < 32) {
        float s = fc1_b[t];
        for (int k = 0; k < 64; k++) s += z1[k] * fc1_w[k * 32 + t];
        z2[t] = s;
    }
    __syncthreads();
    if (t < 16) {
        float s = fc2_b[t];
        for (int k = 0; k < 32; k++) s += z2[k] * fc2_w[k * 16 + t];
        z3[t] = s;
    }
    __syncthreads();
    if (t < 8) {
        float s = fc3_b[t];
        for (int k = 0; k < 16; k++) s += z3[k] * fc3_w[k * 8 + t];
        z4[t] = s;
    }
    __syncthreads();
    if (t < 2) {
        float s = fc4_b[t];
        for (int k = 0; k < 8; k++) s += z4[k] * fc4_w[k * 2 + t];
        z5[t] = s;
    }
    __syncthreads();
    if (t == 0) out[g] = z5[0] * fc5_w[0] + z5[1] * fc5_w[1] + fc5_b[0];
}

// ---------------- launch ----------------
extern "C" void kernel_launch(void* const* d_in, const int* in_sizes, int n_in,
                              void* d_out, int out_size) {
    const float* x      = (const float*)d_in[0];
    const int*   src    = (const int*)d_in[1];
    const int*   dst    = (const int*)d_in[2];
    const int*   batch  = (const int*)d_in[3];
    const float* g1_w1  = (const float*)d_in[4];
    const float* g1_b1  = (const float*)d_in[5];
    const float* g1_w2  = (const float*)d_in[6];
    const float* g1_b2  = (const float*)d_in[7];
    const float* bn1_g  = (const float*)d_in[8];
    const float* bn1_b  = (const float*)d_in[9];
    const float* g2_w1  = (const float*)d_in[10];
    const float* g2_b1  = (const float*)d_in[11];
    const float* g2_w2  = (const float*)d_in[12];
    const float* g2_b2  = (const float*)d_in[13];
    const float* bn2_g  = (const float*)d_in[14];
    const float* bn2_b  = (const float*)d_in[15];
    const float* fcxd_w = (const float*)d_in[16];
    const float* fcxd_b = (const float*)d_in[17];
    const float* fc1_w  = (const float*)d_in[18];
    const float* fc1_b  = (const float*)d_in[19];
    const float* fc2_w  = (const float*)d_in[20];
    const float* fc2_b  = (const float*)d_in[21];
    const float* fc3_w  = (const float*)d_in[22];
    const float* fc3_b  = (const float*)d_in[23];
    const float* fc4_w  = (const float*)d_in[24];
    const float* fc4_b  = (const float*)d_in[25];
    const float* fc5_w  = (const float*)d_in[26];
    const float* fc5_b  = (const float*)d_in[27];
    float* out = (float*)d_out;

    const int E = in_sizes[1];
    const int M = NN;

    __half* Y1h;
    float *H, *Y2;
    cudaGetSymbolAddress((void**)&Y1h, g_Y1h);
    cudaGetSymbolAddress((void**)&H,   g_H);
    cudaGetSymbolAddress((void**)&Y2,  g_Y2);

    static cudaStream_t s_side = nullptr;
    static cudaEvent_t ev_fork = nullptr, ev_join = nullptr;
    if (s_side == nullptr) {
        cudaStreamCreateWithFlags(&s_side, cudaStreamNonBlocking);
        cudaEventCreateWithFlags(&ev_fork, cudaEventDisableTiming);
        cudaEventCreateWithFlags(&ev_join, cudaEventDisableTiming);
    }

    // fork side stream (CSR build)
    cudaEventRecord(ev_fork, 0);
    cudaStreamWaitEvent(s_side, ev_fork, 0);
    hist_kernel<<<(E + 255) / 256, 256, 0, s_side>>>(dst, E);
    scanA_kernel<<<SCAN_NBLK, SCAN_BLK, 0, s_side>>>();
    scanC_kernel<<<SCAN_NBLK, SCAN_BLK, 0, s_side>>>();

    // main: Y1h = fp16(x @ W11) (zeroes stats1)
    gemm112_kernel<<<(M + 127) / 128, 256>>>(x, g1_w1, Y1h, M);

    fill_kernel<<<(E + 255) / 256, 256, 0, s_side>>>(src, dst, E);
    cudaEventRecord(ev_join, s_side);
    cudaStreamWaitEvent(0, ev_join, 0);

    // fused layer-1 tail (fp16 gather)
    aggGemm112_kernel<<<(M + 63) / 64, 256>>>(Y1h, g1_b1, g1_w2, g1_b2, H, M);

    // layer 2
    gemmY2_kernel<<<(M + 63) / 64, 256>>>(H, g2_w1, bn1_g, bn1_b, Y2, M);
    gemmagg32_kernel<<<(M + 63) / 64, 256>>>(Y2, g2_b1, g2_w2, g2_b2, batch, M);

    // head
    head_kernel<<<NG, 64>>>(bn2_g, bn2_b, fcxd_w, fcxd_b, fc1_w, fc1_b, fc2_w, fc2_b,
                            fc3_w, fc3_b, fc4_w, fc4_b, fc5_w, fc5_b, out);
}